// round 14
// baseline (speedup 1.0000x reference)
#include <cuda_runtime.h>
#include <math_constants.h>

#define NN 512
#define DIMX 256
#define NH 8
#define DH 64
#define INNER 512
#define NR 66
#define PI_F 3.14159265358979f
#define SCALE_F 0.125f
#define INV_NORM (1.0f/51.0f)
#define DSTEP_F (7.0f*PI_F/15.0f)
#define KSPLIT 4

typedef unsigned long long ull;

// ---------------- scratch ----------------
__device__ float g_q [NN*INNER];
__device__ float g_kc[NN*INNER];
__device__ float g_v [NN*INNER];
__device__ float g_P [NN*NR*NH];                 // [i][r][h]
__device__ float g_sc[(size_t)NN*NH*NN];         // scores/attn, [i][h][j]
__device__ float g_ao[KSPLIT*(size_t)NN*INNER];  // split-K partials [s][i][hd]

// ---------------- tf32 mma helpers ------------------------------------
static __device__ __forceinline__ unsigned f2t(float x) {
    unsigned u;
    asm("cvt.rna.tf32.f32 %0, %1;" : "=r"(u) : "f"(x));
    return u;
}
static __device__ __forceinline__ void mma8(float* c, const unsigned* a, const unsigned* b) {
    asm volatile(
        "mma.sync.aligned.m16n8k8.row.col.f32.tf32.tf32.f32 "
        "{%0,%1,%2,%3}, {%4,%5,%6,%7}, {%8,%9}, {%0,%1,%2,%3};"
        : "+f"(c[0]), "+f"(c[1]), "+f"(c[2]), "+f"(c[3])
        : "r"(a[0]), "r"(a[1]), "r"(a[2]), "r"(a[3]), "r"(b[0]), "r"(b[1]));
}
static __device__ __forceinline__ uint4 f2t4(float4 v) {
    return make_uint4(f2t(v.x), f2t(v.y), f2t(v.z), f2t(v.w));
}

// ---------------- f32x2 packed helpers ---------------------------------
static __device__ __forceinline__ ull pk2(float x) {
    ull d; unsigned u = __float_as_uint(x);
    asm("mov.b64 %0, {%1, %1};" : "=l"(d) : "r"(u));
    return d;
}
static __device__ __forceinline__ ull fma2(ull a, ull b, ull c) {
    ull d;
    asm("fma.rn.f32x2 %0, %1, %2, %3;" : "=l"(d) : "l"(a), "l"(b), "l"(c));
    return d;
}
static __device__ __forceinline__ float2 up2(ull d) {
    unsigned lo, hi;
    asm("mov.b64 {%0, %1}, %2;" : "=r"(lo), "=r"(hi) : "l"(d));
    return make_float2(__uint_as_float(lo), __uint_as_float(hi));
}

#define STAGE_U (2 * 64 * 68)
#define DB_SMEM (2 * STAGE_U * 4)

// ---------------- K1: QKV projections (tf32 mma, double-buffered) ------
__global__ void __launch_bounds__(128) qkv_kernel(const float* __restrict__ x,
                           const float* __restrict__ Wq,
                           const float* __restrict__ Wk,
                           const float* __restrict__ Wv) {
    extern __shared__ unsigned dynq[];
    const float* W = (blockIdx.z == 0) ? Wq : ((blockIdx.z == 1) ? Wk : Wv);
    float* out = (blockIdx.z == 0) ? g_q : ((blockIdx.z == 1) ? g_kc : g_v);
    const int n0 = blockIdx.x * 64, m0 = blockIdx.y * 64;
    const int tid = threadIdx.x, w = tid >> 5, lane = tid & 31;
    const int wm = w & 1, wn = w >> 1;
    const int gid = lane >> 2, tig = lane & 3;

    auto load_stage = [&](int st, int ch) {
        unsigned (*As)[68] = (unsigned(*)[68])(dynq + st * STAGE_U);
        unsigned (*Bs)[68] = (unsigned(*)[68])(dynq + st * STAGE_U + 64 * 68);
        const int kb = ch * 64;
#pragma unroll
        for (int i = 0; i < 8; i++) {
            int slot = tid + i * 128;
            int row = slot >> 4, c4 = slot & 15;
            float4 av = *(const float4*)&x[(size_t)(m0 + row) * DIMX + kb + c4 * 4];
            *(uint4*)&As[row][c4 * 4] = f2t4(av);
            float4 bv = *(const float4*)&W[(size_t)(kb + row) * INNER + n0 + c4 * 4];
            *(uint4*)&Bs[row][c4 * 4] = f2t4(bv);
        }
    };

    float c[2][4][4] = {};
    load_stage(0, 0);
    __syncthreads();
    for (int ch = 0; ch < 4; ch++) {
        if (ch < 3) load_stage((ch + 1) & 1, ch + 1);
        unsigned (*As)[68] = (unsigned(*)[68])(dynq + (ch & 1) * STAGE_U);
        unsigned (*Bs)[68] = (unsigned(*)[68])(dynq + (ch & 1) * STAGE_U + 64 * 68);
#pragma unroll
        for (int kk = 0; kk < 8; kk++) {
            const int k0 = kk * 8;
            unsigned a[2][4], b[4][2];
#pragma unroll
            for (int am = 0; am < 2; am++) {
                int rb = wm * 32 + am * 16;
                a[am][0] = As[rb + gid][k0 + tig];
                a[am][1] = As[rb + gid + 8][k0 + tig];
                a[am][2] = As[rb + gid][k0 + tig + 4];
                a[am][3] = As[rb + gid + 8][k0 + tig + 4];
            }
#pragma unroll
            for (int an = 0; an < 4; an++) {
                int cb = wn * 32 + an * 8;
                b[an][0] = Bs[k0 + tig][cb + gid];
                b[an][1] = Bs[k0 + tig + 4][cb + gid];
            }
#pragma unroll
            for (int am = 0; am < 2; am++)
#pragma unroll
                for (int an = 0; an < 4; an++)
                    mma8(c[am][an], a[am], b[an]);
        }
        __syncthreads();
    }
#pragma unroll
    for (int am = 0; am < 2; am++) {
        int r0 = m0 + wm * 32 + am * 16 + gid;
#pragma unroll
        for (int an = 0; an < 4; an++) {
            int cc = n0 + wn * 32 + an * 8 + tig * 2;
            *(float2*)&out[(size_t)r0 * INNER + cc] = make_float2(c[am][an][0], c[am][an][1]);
            *(float2*)&out[(size_t)(r0 + 8) * INNER + cc] = make_float2(c[am][an][2], c[am][an][3]);
        }
    }
}

// ---------------- K2: content scores (tf32, z<8) + P (z==8), 128 thr ---
__global__ void __launch_bounds__(128) cs_p_kernel(const float* __restrict__ Wk) {
    __shared__ unsigned sm[2 * 64 * 68];
    const int tid = threadIdx.x;
    if (blockIdx.z < 8) {
        unsigned (*Qs)[68] = (unsigned(*)[68])sm;
        unsigned (*Ks)[68] = (unsigned(*)[68])(sm + 64 * 68);
        const int h = blockIdx.z;
        const int j0 = blockIdx.x * 64, i0 = blockIdx.y * 64;
        const int w = tid >> 5, lane = tid & 31;
        const int wm = w & 1, wn = w >> 1;
        const int gid = lane >> 2, tig = lane & 3;

#pragma unroll
        for (int i = 0; i < 8; i++) {
            int slot = tid + i * 128;
            int row = slot >> 4, c4 = slot & 15;
            float4 qv = *(const float4*)&g_q [(size_t)(i0 + row) * INNER + h * DH + c4 * 4];
            *(uint4*)&Qs[row][c4 * 4] = f2t4(qv);
            float4 kv = *(const float4*)&g_kc[(size_t)(j0 + row) * INNER + h * DH + c4 * 4];
            *(uint4*)&Ks[row][c4 * 4] = f2t4(kv);
        }
        __syncthreads();

        float c[2][4][4] = {};
#pragma unroll
        for (int kk = 0; kk < 8; kk++) {
            const int k0 = kk * 8;
            unsigned a[2][4], b[4][2];
#pragma unroll
            for (int am = 0; am < 2; am++) {
                int rb = wm * 32 + am * 16;
                a[am][0] = Qs[rb + gid][k0 + tig];
                a[am][1] = Qs[rb + gid + 8][k0 + tig];
                a[am][2] = Qs[rb + gid][k0 + tig + 4];
                a[am][3] = Qs[rb + gid + 8][k0 + tig + 4];
            }
#pragma unroll
            for (int an = 0; an < 4; an++) {
                int cb = wn * 32 + an * 8;
                b[an][0] = Ks[cb + gid][k0 + tig];
                b[an][1] = Ks[cb + gid][k0 + tig + 4];
            }
#pragma unroll
            for (int am = 0; am < 2; am++)
#pragma unroll
                for (int an = 0; an < 4; an++)
                    mma8(c[am][an], a[am], b[an]);
        }
#pragma unroll
        for (int am = 0; am < 2; am++) {
            int r0 = i0 + wm * 32 + am * 16 + gid;
#pragma unroll
            for (int an = 0; an < 4; an++) {
                int cc = j0 + wn * 32 + an * 8 + tig * 2;
                float* d0 = &g_sc[((size_t)r0 * NH + h) * NN + cc];
                float* d1 = &g_sc[((size_t)(r0 + 8) * NH + h) * NN + cc];
                *(float2*)d0 = make_float2(c[am][an][0] * SCALE_F, c[am][an][1] * SCALE_F);
                *(float2*)d1 = make_float2(c[am][an][2] * SCALE_F, c[am][an][3] * SCALE_F);
            }
        }
    } else {
        // P[i][r][h] for 8 queries, 128 threads
        float* qs = (float*)sm;   // [8][512] = 16 KB
        const int i0 = (blockIdx.y * 8 + blockIdx.x) * 8;
        const float4* src = (const float4*)(g_q + (size_t)i0 * INNER);
#pragma unroll
        for (int u = 0; u < 8; u++) ((float4*)qs)[tid + u * 128] = src[tid + u * 128];
        __syncthreads();
        for (int tt = tid; tt < 528; tt += 128) {
            int r = tt >> 3, h = tt & 7;
            const float4* w4 = (const float4*)(Wk + (size_t)(DIMX + r) * INNER + h * DH);
            float acc[8] = {};
#pragma unroll
            for (int u = 0; u < 16; u++) {
                float4 wv = w4[u];
#pragma unroll
                for (int i = 0; i < 8; i++) {
                    float4 qv = *(const float4*)&qs[i * INNER + h * DH + u * 4];
                    acc[i] += wv.x*qv.x + wv.y*qv.y + wv.z*qv.z + wv.w*qv.w;
                }
            }
#pragma unroll
            for (int i = 0; i < 8; i++)
                g_P[((size_t)(i0 + i) * NR + r) * NH + h] = acc[i];
        }
    }
}

// ---------------- K3: RPE features + score add + softmax (f32x2) ------
__global__ void __launch_bounds__(256, 3) rpe_softmax_kernel(const float* __restrict__ pos) {
    const int i = blockIdx.x;
    __shared__ float Ps[NR * NH];
    __shared__ float s_s[NH][NN];
    const int tid = threadIdx.x;
    for (int t = tid; t < NR * NH; t += 256) Ps[t] = g_P[(size_t)i * NR * NH + t];
    __syncthreads();

    const float2 pq = ((const float2*)pos)[i];
    const ulonglong2* Pu2 = reinterpret_cast<const ulonglong2*>(Ps);

    const int ja = tid * 2;
    const float4 pk = *(const float4*)&pos[ja * 2];
    float dxa = (pk.x - pq.x) * INV_NORM; dxa = __fdividef(dxa, 1.f + fabsf(dxa));
    float dya = (pk.y - pq.y) * INV_NORM; dya = __fdividef(dya, 1.f + fabsf(dya));
    float dxb = (pk.z - pq.x) * INV_NORM; dxb = __fdividef(dxb, 1.f + fabsf(dxb));
    float dyb = (pk.w - pq.y) * INV_NORM; dyb = __fdividef(dyb, 1.f + fabsf(dyb));

    ull A0v[4] = {}, A1v[4] = {};

    {
        float sa, ca, sb, cb, sda, cda, sdb, cdb;
        __sincosf(dxa * PI_F, &sa, &ca);  __sincosf(dxa * DSTEP_F, &sda, &cda);
        __sincosf(dxb * PI_F, &sb, &cb);  __sincosf(dxb * DSTEP_F, &sdb, &cdb);
#pragma unroll
        for (int k = 0; k < 16; k++) {
            ulonglong2 pA = Pu2[2 * k],        pB = Pu2[2 * k + 1];
            ulonglong2 qA = Pu2[2 * (16 + k)], qB = Pu2[2 * (16 + k) + 1];
            ull sa2 = pk2(sa), ca2 = pk2(ca), sb2 = pk2(sb), cb2 = pk2(cb);
            A0v[0] = fma2(sa2, pA.x, A0v[0]); A0v[1] = fma2(sa2, pA.y, A0v[1]);
            A0v[2] = fma2(sa2, pB.x, A0v[2]); A0v[3] = fma2(sa2, pB.y, A0v[3]);
            A0v[0] = fma2(ca2, qA.x, A0v[0]); A0v[1] = fma2(ca2, qA.y, A0v[1]);
            A0v[2] = fma2(ca2, qB.x, A0v[2]); A0v[3] = fma2(ca2, qB.y, A0v[3]);
            A1v[0] = fma2(sb2, pA.x, A1v[0]); A1v[1] = fma2(sb2, pA.y, A1v[1]);
            A1v[2] = fma2(sb2, pB.x, A1v[2]); A1v[3] = fma2(sb2, pB.y, A1v[3]);
            A1v[0] = fma2(cb2, qA.x, A1v[0]); A1v[1] = fma2(cb2, qA.y, A1v[1]);
            A1v[2] = fma2(cb2, qB.x, A1v[2]); A1v[3] = fma2(cb2, qB.y, A1v[3]);
            float ns = sa*cda + ca*sda, nc = ca*cda - sa*sda; sa = ns; ca = nc;
            ns = sb*cdb + cb*sdb; nc = cb*cdb - sb*sdb; sb = ns; cb = nc;
        }
        ulonglong2 pA = Pu2[2 * 32], pB = Pu2[2 * 32 + 1];
        ull da2 = pk2(dxa), db2 = pk2(dxb);
        A0v[0] = fma2(da2, pA.x, A0v[0]); A0v[1] = fma2(da2, pA.y, A0v[1]);
        A0v[2] = fma2(da2, pB.x, A0v[2]); A0v[3] = fma2(da2, pB.y, A0v[3]);
        A1v[0] = fma2(db2, pA.x, A1v[0]); A1v[1] = fma2(db2, pA.y, A1v[1]);
        A1v[2] = fma2(db2, pB.x, A1v[2]); A1v[3] = fma2(db2, pB.y, A1v[3]);
    }
    {
        float sa, ca, sb, cb, sda, cda, sdb, cdb;
        __sincosf(dya * PI_F, &sa, &ca);  __sincosf(dya * DSTEP_F, &sda, &cda);
        __sincosf(dyb * PI_F, &sb, &cb);  __sincosf(dyb * DSTEP_F, &sdb, &cdb);
#pragma unroll
        for (int k = 0; k < 16; k++) {
            ulonglong2 pA = Pu2[2 * (33 + k)], pB = Pu2[2 * (33 + k) + 1];
            ulonglong2 qA = Pu2[2 * (49 + k)], qB = Pu2[2 * (49 + k) + 1];
            ull sa2 = pk2(sa), ca2 = pk2(ca), sb2 = pk2(sb), cb2 = pk2(cb);
            A0v[0] = fma2(sa2, pA.x, A0v[0]); A0v[1] = fma2(sa2, pA.y, A0v[1]);
            A0v[2] = fma2(sa2, pB.x, A0v[2]); A0v[3] = fma2(sa2, pB.y, A0v[3]);
            A0v[0] = fma2(ca2, qA.x, A0v[0]); A0v[1] = fma2(ca2, qA.y, A0v[1]);
            A0v[2] = fma2(ca2, qB.x, A0v[2]); A0v[3] = fma2(ca2, qB.y, A0v[3]);
            A1v[0] = fma2(sb2, pA.x, A1v[0]); A1v[1] = fma2(sb2, pA.y, A1v[1]);
            A1v[2] = fma2(sb2, pB.x, A1v[2]); A1v[3] = fma2(sb2, pB.y, A1v[3]);
            A1v[0] = fma2(cb2, qA.x, A1v[0]); A1v[1] = fma2(cb2, qA.y, A1v[1]);
            A1v[2] = fma2(cb2, qB.x, A1v[2]); A1v[3] = fma2(cb2, qB.y, A1v[3]);
            float ns = sa*cda + ca*sda, nc = ca*cda - sa*sda; sa = ns; ca = nc;
            ns = sb*cdb + cb*sdb; nc = cb*cdb - sb*sdb; sb = ns; cb = nc;
        }
        ulonglong2 pA = Pu2[2 * 65], pB = Pu2[2 * 65 + 1];
        ull da2 = pk2(dya), db2 = pk2(dyb);
        A0v[0] = fma2(da2, pA.x, A0v[0]); A0v[1] = fma2(da2, pA.y, A0v[1]);
        A0v[2] = fma2(da2, pB.x, A0v[2]); A0v[3] = fma2(da2, pB.y, A0v[3]);
        A1v[0] = fma2(db2, pA.x, A1v[0]); A1v[1] = fma2(db2, pA.y, A1v[1]);
        A1v[2] = fma2(db2, pB.x, A1v[2]); A1v[3] = fma2(db2, pB.y, A1v[3]);
    }

    const float* csrow = g_sc + (size_t)i * NH * NN;
#pragma unroll
    for (int hp = 0; hp < 4; hp++) {
        float2 a0 = up2(A0v[hp]);
        float2 a1 = up2(A1v[hp]);
        int h0 = hp * 2, h1 = hp * 2 + 1;
        float2 cs0 = *(const float2*)&csrow[h0 * NN + ja];
        float2 cs1 = *(const float2*)&csrow[h1 * NN + ja];
        *(float2*)&s_s[h0][ja] = make_float2(cs0.x + a0.x * SCALE_F, cs0.y + a1.x * SCALE_F);
        *(float2*)&s_s[h1][ja] = make_float2(cs1.x + a0.y * SCALE_F, cs1.y + a1.y * SCALE_F);
    }
    __syncthreads();

    const int w = tid >> 5, lane = tid & 31;
    float4* s4 = (float4*)s_s[w];
    float m = -CUDART_INF_F;
#pragma unroll
    for (int t = 0; t < 4; t++) {
        float4 v = s4[lane + t * 32];
        m = fmaxf(m, fmaxf(fmaxf(v.x, v.y), fmaxf(v.z, v.w)));
    }
#pragma unroll
    for (int o = 16; o; o >>= 1) m = fmaxf(m, __shfl_xor_sync(0xffffffffu, m, o));
    float sum = 0.f;
#pragma unroll
    for (int t = 0; t < 4; t++) {
        float4 v = s4[lane + t * 32];
        v.x = __expf(v.x - m); v.y = __expf(v.y - m);
        v.z = __expf(v.z - m); v.w = __expf(v.w - m);
        s4[lane + t * 32] = v;
        sum += v.x + v.y + v.z + v.w;
    }
#pragma unroll
    for (int o = 16; o; o >>= 1) sum += __shfl_xor_sync(0xffffffffu, sum, o);
    const float inv = __fdividef(1.0f, sum);
    float4* arow = (float4*)(g_sc + (size_t)i * NH * NN + (size_t)w * NN);
#pragma unroll
    for (int t = 0; t < 4; t++) {
        float4 v = s4[lane + t * 32];
        arow[lane + t * 32] = make_float4(v.x * inv, v.y * inv, v.z * inv, v.w * inv);
    }
}

// ---------------- K4: attn @ V (tf32, 256 thr), split-K=4 --------------
__global__ void __launch_bounds__(256) av_kernel() {
    __shared__ unsigned At[64][68];
    __shared__ unsigned Vs[64][68];
    const int i0 = blockIdx.x * 64;
    const int h  = blockIdx.y;
    const int s  = blockIdx.z;
    const int kbase = s * 128;
    const int tid = threadIdx.x, w = tid >> 5, lane = tid & 31;
    const int wm = w & 1, wn = w >> 1;
    const int gid = lane >> 2, tig = lane & 3;

    float c[2][2][4] = {};
    for (int ch = 0; ch < 2; ch++) {
        const int kb = kbase + ch * 64;
#pragma unroll
        for (int i = 0; i < 4; i++) {
            int slot = tid + i * 256;
            int row = slot >> 4, c4 = slot & 15;
            float4 av = *(const float4*)&g_sc[((size_t)(i0 + row) * NH + h) * NN + kb + c4 * 4];
            *(uint4*)&At[row][c4 * 4] = f2t4(av);
            float4 vv = *(const float4*)&g_v[(size_t)(kb + row) * INNER + h * DH + c4 * 4];
            *(uint4*)&Vs[row][c4 * 4] = f2t4(vv);
        }
        __syncthreads();
#pragma unroll
        for (int kk = 0; kk < 8; kk++) {
            const int k0 = kk * 8;
            unsigned a[2][4], b[2][2];
#pragma unroll
            for (int am = 0; am < 2; am++) {
                int rb = wm * 32 + am * 16;
                a[am][0] = At[rb + gid][k0 + tig];
                a[am][1] = At[rb + gid + 8][k0 + tig];
                a[am][2] = At[rb + gid][k0 + tig + 4];
                a[am][3] = At[rb + gid + 8][k0 + tig + 4];
            }
#pragma unroll
            for (int an = 0; an < 2; an++) {
                int cb = wn * 16 + an * 8;
                b[an][0] = Vs[k0 + tig][cb + gid];
                b[an][1] = Vs[k0 + tig + 4][cb + gid];
            }
#pragma unroll
            for (int am = 0; am < 2; am++)
#pragma unroll
                for (int an = 0; an < 2; an++)
                    mma8(c[am][an], a[am], b[an]);
        }
        __syncthreads();
    }
#pragma unroll
    for (int am = 0; am < 2; am++) {
        int r0 = i0 + wm * 32 + am * 16 + gid;
#pragma unroll
        for (int an = 0; an < 2; an++) {
            int cc = h * DH + wn * 16 + an * 8 + tig * 2;
            float* d0 = &g_ao[((size_t)s * NN + r0) * INNER + cc];
            float* d1 = &g_ao[((size_t)s * NN + r0 + 8) * INNER + cc];
            *(float2*)d0 = make_float2(c[am][an][0], c[am][an][1]);
            *(float2*)d1 = make_float2(c[am][an][2], c[am][an][3]);
        }
    }
}

// ---------------- K5: out = (sum_s ao_s) @ Wo + bo (tf32, 128 thr) -----
__global__ void __launch_bounds__(128) out_kernel(const float* __restrict__ Wo,
                           const float* __restrict__ bo,
                           float* __restrict__ out) {
    __shared__ unsigned As[32][68];
    __shared__ unsigned Bs[64][68];
    const int n0 = blockIdx.x * 64;
    const int i0 = blockIdx.y * 32;
    const int tid = threadIdx.x, w = tid >> 5, lane = tid & 31;
    const int wm = w & 1, wn = w >> 1;
    const int gid = lane >> 2, tig = lane & 3;

    float c[4][4] = {};
    for (int ch = 0; ch < 8; ch++) {
        const int kb = ch * 64;
#pragma unroll
        for (int i = 0; i < 4; i++) {
            int slot = tid + i * 128;
            int row = slot >> 4, c4 = slot & 15;
            const float* base = g_ao + (size_t)(i0 + row) * INNER + kb + c4 * 4;
            float4 u0 = *(const float4*)(base);
            float4 u1 = *(const float4*)(base + (size_t)NN * INNER);
            float4 u2 = *(const float4*)(base + 2 * (size_t)NN * INNER);
            float4 u3 = *(const float4*)(base + 3 * (size_t)NN * INNER);
            float4 sum = make_float4(u0.x+u1.x+u2.x+u3.x, u0.y+u1.y+u2.y+u3.y,
                                     u0.z+u1.z+u2.z+u3.z, u0.w+u1.w+u2.w+u3.w);
            *(uint4*)&As[row][c4 * 4] = f2t4(sum);
        }
#pragma unroll
        for (int i = 0; i < 8; i++) {
            int slot = tid + i * 128;
            int row = slot >> 4, c4 = slot & 15;
            float4 bv = *(const float4*)&Wo[(size_t)(kb + row) * DIMX + n0 + c4 * 4];
            *(uint4*)&Bs[row][c4 * 4] = f2t4(bv);
        }
        __syncthreads();
#pragma unroll
        for (int kk = 0; kk < 8; kk++) {
            const int k0 = kk * 8;
            unsigned a[4], b[4][2];
            int rb = wm * 16;
            a[0] = As[rb + gid][k0 + tig];
            a[1] = As[rb + gid + 8][k0 + tig];
            a[2] = As[rb + gid][k0 + tig + 4];
            a[3] = As[rb + gid + 8][k0 + tig + 4];
#pragma unroll
            for (int an = 0; an < 4; an++) {
                int cb = wn * 32 + an * 8;
                b[an][0] = Bs[k0 + tig][cb + gid];
                b[an][1] = Bs[k0 + tig + 4][cb + gid];
            }
#pragma unroll
            for (int an = 0; an < 4; an++)
                mma8(c[an], a, b[an]);
        }
        __syncthreads();
    }
    int r0 = i0 + wm * 16 + gid;
#pragma unroll
    for (int an = 0; an < 4; an++) {
        int cc = n0 + wn * 32 + an * 8 + tig * 2;
        float b0 = bo[cc], b1 = bo[cc + 1];
        *(float2*)&out[(size_t)r0 * DIMX + cc] = make_float2(c[an][0] + b0, c[an][1] + b1);
        *(float2*)&out[(size_t)(r0 + 8) * DIMX + cc] = make_float2(c[an][2] + b0, c[an][3] + b1);
    }
}

// ---------------- launch ----------------------------------------------
extern "C" void kernel_launch(void* const* d_in, const int* in_sizes, int n_in,
                              void* d_out, int out_size) {
    const float* x   = (const float*)d_in[0];
    const float* pos = (const float*)d_in[1];
    const float* Wq  = (const float*)d_in[2];
    const float* Wk  = (const float*)d_in[3];
    const float* Wv  = (const float*)d_in[4];
    const float* Wo  = (const float*)d_in[5];
    const float* bo  = (const float*)d_in[6];
    float* out = (float*)d_out;

    cudaFuncSetAttribute(qkv_kernel, cudaFuncAttributeMaxDynamicSharedMemorySize, DB_SMEM);

    qkv_kernel<<<dim3(8, 8, 3), 128, DB_SMEM>>>(x, Wq, Wk, Wv);
    cs_p_kernel<<<dim3(8, 8, 9), 128>>>(Wk);
    rpe_softmax_kernel<<<512, 256>>>(pos);
    av_kernel<<<dim3(8, 8, KSPLIT), 256>>>();
    out_kernel<<<dim3(4, 16), 128>>>(Wo, bo, out);
}

// round 15
// speedup vs baseline: 1.2106x; 1.2106x over previous
#include <cuda_runtime.h>
#include <math_constants.h>

#define NN 512
#define DIMX 256
#define NH 8
#define DH 64
#define INNER 512
#define NR 66
#define PI_F 3.14159265358979f
#define SCALE_F 0.125f
#define INV_NORM (1.0f/51.0f)
#define DSTEP_F (7.0f*PI_F/15.0f)
#define KSPLIT 4

typedef unsigned long long ull;

// ---------------- scratch ----------------
__device__ float g_q [NN*INNER];
__device__ float g_kc[NN*INNER];
__device__ float g_v [NN*INNER];
__device__ float g_P [NN*NR*NH];                 // [i][r][h]
__device__ float g_sc[(size_t)NN*NH*NN];         // scores/attn, [i][h][j]
__device__ float g_ao[KSPLIT*(size_t)NN*INNER];  // split-K partials [s][i][hd]

// ---------------- tf32 mma helpers ------------------------------------
static __device__ __forceinline__ unsigned f2t(float x) {
    unsigned u;
    asm("cvt.rna.tf32.f32 %0, %1;" : "=r"(u) : "f"(x));
    return u;
}
static __device__ __forceinline__ void mma8(float* c, const unsigned* a, const unsigned* b) {
    asm volatile(
        "mma.sync.aligned.m16n8k8.row.col.f32.tf32.tf32.f32 "
        "{%0,%1,%2,%3}, {%4,%5,%6,%7}, {%8,%9}, {%0,%1,%2,%3};"
        : "+f"(c[0]), "+f"(c[1]), "+f"(c[2]), "+f"(c[3])
        : "r"(a[0]), "r"(a[1]), "r"(a[2]), "r"(a[3]), "r"(b[0]), "r"(b[1]));
}
static __device__ __forceinline__ uint4 f2t4(float4 v) {
    return make_uint4(f2t(v.x), f2t(v.y), f2t(v.z), f2t(v.w));
}

// ---------------- f32x2 packed helpers ---------------------------------
static __device__ __forceinline__ ull pk2(float x) {
    ull d; unsigned u = __float_as_uint(x);
    asm("mov.b64 %0, {%1, %1};" : "=l"(d) : "r"(u));
    return d;
}
static __device__ __forceinline__ ull fma2(ull a, ull b, ull c) {
    ull d;
    asm("fma.rn.f32x2 %0, %1, %2, %3;" : "=l"(d) : "l"(a), "l"(b), "l"(c));
    return d;
}
static __device__ __forceinline__ float2 up2(ull d) {
    unsigned lo, hi;
    asm("mov.b64 {%0, %1}, %2;" : "=r"(lo), "=r"(hi) : "l"(d));
    return make_float2(__uint_as_float(lo), __uint_as_float(hi));
}

#define STAGE_U (2 * 64 * 68)
#define DB_SMEM (2 * STAGE_U * 4)

// ---------------- K1: QKV projections (tf32 mma, double-buffered) ------
__global__ void __launch_bounds__(128) qkv_kernel(const float* __restrict__ x,
                           const float* __restrict__ Wq,
                           const float* __restrict__ Wk,
                           const float* __restrict__ Wv) {
    extern __shared__ unsigned dynq[];
    const float* W = (blockIdx.z == 0) ? Wq : ((blockIdx.z == 1) ? Wk : Wv);
    float* out = (blockIdx.z == 0) ? g_q : ((blockIdx.z == 1) ? g_kc : g_v);
    const int n0 = blockIdx.x * 64, m0 = blockIdx.y * 64;
    const int tid = threadIdx.x, w = tid >> 5, lane = tid & 31;
    const int wm = w & 1, wn = w >> 1;
    const int gid = lane >> 2, tig = lane & 3;

    auto load_stage = [&](int st, int ch) {
        unsigned (*As)[68] = (unsigned(*)[68])(dynq + st * STAGE_U);
        unsigned (*Bs)[68] = (unsigned(*)[68])(dynq + st * STAGE_U + 64 * 68);
        const int kb = ch * 64;
#pragma unroll
        for (int i = 0; i < 8; i++) {
            int slot = tid + i * 128;
            int row = slot >> 4, c4 = slot & 15;
            float4 av = *(const float4*)&x[(size_t)(m0 + row) * DIMX + kb + c4 * 4];
            *(uint4*)&As[row][c4 * 4] = f2t4(av);
            float4 bv = *(const float4*)&W[(size_t)(kb + row) * INNER + n0 + c4 * 4];
            *(uint4*)&Bs[row][c4 * 4] = f2t4(bv);
        }
    };

    float c[2][4][4] = {};
    load_stage(0, 0);
    __syncthreads();
    for (int ch = 0; ch < 4; ch++) {
        if (ch < 3) load_stage((ch + 1) & 1, ch + 1);
        unsigned (*As)[68] = (unsigned(*)[68])(dynq + (ch & 1) * STAGE_U);
        unsigned (*Bs)[68] = (unsigned(*)[68])(dynq + (ch & 1) * STAGE_U + 64 * 68);
#pragma unroll
        for (int kk = 0; kk < 8; kk++) {
            const int k0 = kk * 8;
            unsigned a[2][4], b[4][2];
#pragma unroll
            for (int am = 0; am < 2; am++) {
                int rb = wm * 32 + am * 16;
                a[am][0] = As[rb + gid][k0 + tig];
                a[am][1] = As[rb + gid + 8][k0 + tig];
                a[am][2] = As[rb + gid][k0 + tig + 4];
                a[am][3] = As[rb + gid + 8][k0 + tig + 4];
            }
#pragma unroll
            for (int an = 0; an < 4; an++) {
                int cb = wn * 32 + an * 8;
                b[an][0] = Bs[k0 + tig][cb + gid];
                b[an][1] = Bs[k0 + tig + 4][cb + gid];
            }
#pragma unroll
            for (int am = 0; am < 2; am++)
#pragma unroll
                for (int an = 0; an < 4; an++)
                    mma8(c[am][an], a[am], b[an]);
        }
        __syncthreads();
    }
#pragma unroll
    for (int am = 0; am < 2; am++) {
        int r0 = m0 + wm * 32 + am * 16 + gid;
#pragma unroll
        for (int an = 0; an < 4; an++) {
            int cc = n0 + wn * 32 + an * 8 + tig * 2;
            *(float2*)&out[(size_t)r0 * INNER + cc] = make_float2(c[am][an][0], c[am][an][1]);
            *(float2*)&out[(size_t)(r0 + 8) * INNER + cc] = make_float2(c[am][an][2], c[am][an][3]);
        }
    }
}

// ---------------- K2: content scores (tf32 mma, 256 thr) ---------------
// grid (8 jtile, 8 itile, 8 head), 8 warps, warp tile 32x16
__global__ void __launch_bounds__(256) cs_kernel() {
    __shared__ unsigned Qs[64][68];
    __shared__ unsigned Ks[64][68];
    const int h = blockIdx.z;
    const int j0 = blockIdx.x * 64, i0 = blockIdx.y * 64;
    const int tid = threadIdx.x, w = tid >> 5, lane = tid & 31;
    const int wm = w & 1, wn = w >> 1;          // wm 0..1, wn 0..3
    const int gid = lane >> 2, tig = lane & 3;

#pragma unroll
    for (int i = 0; i < 4; i++) {
        int slot = tid + i * 256;
        int row = slot >> 4, c4 = slot & 15;
        float4 qv = *(const float4*)&g_q [(size_t)(i0 + row) * INNER + h * DH + c4 * 4];
        *(uint4*)&Qs[row][c4 * 4] = f2t4(qv);
        float4 kv = *(const float4*)&g_kc[(size_t)(j0 + row) * INNER + h * DH + c4 * 4];
        *(uint4*)&Ks[row][c4 * 4] = f2t4(kv);
    }
    __syncthreads();

    float c[2][2][4] = {};
#pragma unroll
    for (int kk = 0; kk < 8; kk++) {
        const int k0 = kk * 8;
        unsigned a[2][4], b[2][2];
#pragma unroll
        for (int am = 0; am < 2; am++) {
            int rb = wm * 32 + am * 16;
            a[am][0] = Qs[rb + gid][k0 + tig];
            a[am][1] = Qs[rb + gid + 8][k0 + tig];
            a[am][2] = Qs[rb + gid][k0 + tig + 4];
            a[am][3] = Qs[rb + gid + 8][k0 + tig + 4];
        }
#pragma unroll
        for (int an = 0; an < 2; an++) {
            int cb = wn * 16 + an * 8;
            b[an][0] = Ks[cb + gid][k0 + tig];
            b[an][1] = Ks[cb + gid][k0 + tig + 4];
        }
#pragma unroll
        for (int am = 0; am < 2; am++)
#pragma unroll
            for (int an = 0; an < 2; an++)
                mma8(c[am][an], a[am], b[an]);
    }
#pragma unroll
    for (int am = 0; am < 2; am++) {
        int r0 = i0 + wm * 32 + am * 16 + gid;
#pragma unroll
        for (int an = 0; an < 2; an++) {
            int cc = j0 + wn * 16 + an * 8 + tig * 2;
            float* d0 = &g_sc[((size_t)r0 * NH + h) * NN + cc];
            float* d1 = &g_sc[((size_t)(r0 + 8) * NH + h) * NN + cc];
            *(float2*)d0 = make_float2(c[am][an][0] * SCALE_F, c[am][an][1] * SCALE_F);
            *(float2*)d1 = make_float2(c[am][an][2] * SCALE_F, c[am][an][3] * SCALE_F);
        }
    }
}

// ---------------- K2b: P[i][r][h] (fp32), 256 blocks x 2 queries -------
__global__ void __launch_bounds__(256) p_kernel(const float* __restrict__ Wk) {
    __shared__ float qs[2 * INNER];
    const int tid = threadIdx.x;
    const int i0 = blockIdx.x * 2;
    const float4* src = (const float4*)(g_q + (size_t)i0 * INNER);
    ((float4*)qs)[tid] = src[tid];
    __syncthreads();
    for (int tt = tid; tt < 528; tt += 256) {
        int r = tt >> 3, h = tt & 7;
        const float4* w4 = (const float4*)(Wk + (size_t)(DIMX + r) * INNER + h * DH);
        float acc0 = 0.f, acc1 = 0.f;
#pragma unroll
        for (int u = 0; u < 16; u++) {
            float4 wv = w4[u];
            float4 q0 = *(const float4*)&qs[h * DH + u * 4];
            float4 q1 = *(const float4*)&qs[INNER + h * DH + u * 4];
            acc0 += wv.x*q0.x + wv.y*q0.y + wv.z*q0.z + wv.w*q0.w;
            acc1 += wv.x*q1.x + wv.y*q1.y + wv.z*q1.z + wv.w*q1.w;
        }
        g_P[((size_t)i0 * NR + r) * NH + h] = acc0;
        g_P[((size_t)(i0 + 1) * NR + r) * NH + h] = acc1;
    }
}

// ---------------- K3: RPE features + score add + softmax (f32x2) ------
__global__ void __launch_bounds__(256, 3) rpe_softmax_kernel(const float* __restrict__ pos) {
    const int i = blockIdx.x;
    __shared__ float Ps[NR * NH];
    __shared__ float s_s[NH][NN];
    const int tid = threadIdx.x;
    for (int t = tid; t < NR * NH; t += 256) Ps[t] = g_P[(size_t)i * NR * NH + t];
    __syncthreads();

    const float2 pq = ((const float2*)pos)[i];
    const ulonglong2* Pu2 = reinterpret_cast<const ulonglong2*>(Ps);

    const int ja = tid * 2;
    const float4 pk = *(const float4*)&pos[ja * 2];
    float dxa = (pk.x - pq.x) * INV_NORM; dxa = __fdividef(dxa, 1.f + fabsf(dxa));
    float dya = (pk.y - pq.y) * INV_NORM; dya = __fdividef(dya, 1.f + fabsf(dya));
    float dxb = (pk.z - pq.x) * INV_NORM; dxb = __fdividef(dxb, 1.f + fabsf(dxb));
    float dyb = (pk.w - pq.y) * INV_NORM; dyb = __fdividef(dyb, 1.f + fabsf(dyb));

    ull A0v[4] = {}, A1v[4] = {};

    {
        float sa, ca, sb, cb, sda, cda, sdb, cdb;
        __sincosf(dxa * PI_F, &sa, &ca);  __sincosf(dxa * DSTEP_F, &sda, &cda);
        __sincosf(dxb * PI_F, &sb, &cb);  __sincosf(dxb * DSTEP_F, &sdb, &cdb);
#pragma unroll
        for (int k = 0; k < 16; k++) {
            ulonglong2 pA = Pu2[2 * k],        pB = Pu2[2 * k + 1];
            ulonglong2 qA = Pu2[2 * (16 + k)], qB = Pu2[2 * (16 + k) + 1];
            ull sa2 = pk2(sa), ca2 = pk2(ca), sb2 = pk2(sb), cb2 = pk2(cb);
            A0v[0] = fma2(sa2, pA.x, A0v[0]); A0v[1] = fma2(sa2, pA.y, A0v[1]);
            A0v[2] = fma2(sa2, pB.x, A0v[2]); A0v[3] = fma2(sa2, pB.y, A0v[3]);
            A0v[0] = fma2(ca2, qA.x, A0v[0]); A0v[1] = fma2(ca2, qA.y, A0v[1]);
            A0v[2] = fma2(ca2, qB.x, A0v[2]); A0v[3] = fma2(ca2, qB.y, A0v[3]);
            A1v[0] = fma2(sb2, pA.x, A1v[0]); A1v[1] = fma2(sb2, pA.y, A1v[1]);
            A1v[2] = fma2(sb2, pB.x, A1v[2]); A1v[3] = fma2(sb2, pB.y, A1v[3]);
            A1v[0] = fma2(cb2, qA.x, A1v[0]); A1v[1] = fma2(cb2, qA.y, A1v[1]);
            A1v[2] = fma2(cb2, qB.x, A1v[2]); A1v[3] = fma2(cb2, qB.y, A1v[3]);
            float ns = sa*cda + ca*sda, nc = ca*cda - sa*sda; sa = ns; ca = nc;
            ns = sb*cdb + cb*sdb; nc = cb*cdb - sb*sdb; sb = ns; cb = nc;
        }
        ulonglong2 pA = Pu2[2 * 32], pB = Pu2[2 * 32 + 1];
        ull da2 = pk2(dxa), db2 = pk2(dxb);
        A0v[0] = fma2(da2, pA.x, A0v[0]); A0v[1] = fma2(da2, pA.y, A0v[1]);
        A0v[2] = fma2(da2, pB.x, A0v[2]); A0v[3] = fma2(da2, pB.y, A0v[3]);
        A1v[0] = fma2(db2, pA.x, A1v[0]); A1v[1] = fma2(db2, pA.y, A1v[1]);
        A1v[2] = fma2(db2, pB.x, A1v[2]); A1v[3] = fma2(db2, pB.y, A1v[3]);
    }
    {
        float sa, ca, sb, cb, sda, cda, sdb, cdb;
        __sincosf(dya * PI_F, &sa, &ca);  __sincosf(dya * DSTEP_F, &sda, &cda);
        __sincosf(dyb * PI_F, &sb, &cb);  __sincosf(dyb * DSTEP_F, &sdb, &cdb);
#pragma unroll
        for (int k = 0; k < 16; k++) {
            ulonglong2 pA = Pu2[2 * (33 + k)], pB = Pu2[2 * (33 + k) + 1];
            ulonglong2 qA = Pu2[2 * (49 + k)], qB = Pu2[2 * (49 + k) + 1];
            ull sa2 = pk2(sa), ca2 = pk2(ca), sb2 = pk2(sb), cb2 = pk2(cb);
            A0v[0] = fma2(sa2, pA.x, A0v[0]); A0v[1] = fma2(sa2, pA.y, A0v[1]);
            A0v[2] = fma2(sa2, pB.x, A0v[2]); A0v[3] = fma2(sa2, pB.y, A0v[3]);
            A0v[0] = fma2(ca2, qA.x, A0v[0]); A0v[1] = fma2(ca2, qA.y, A0v[1]);
            A0v[2] = fma2(ca2, qB.x, A0v[2]); A0v[3] = fma2(ca2, qB.y, A0v[3]);
            A1v[0] = fma2(sb2, pA.x, A1v[0]); A1v[1] = fma2(sb2, pA.y, A1v[1]);
            A1v[2] = fma2(sb2, pB.x, A1v[2]); A1v[3] = fma2(sb2, pB.y, A1v[3]);
            A1v[0] = fma2(cb2, qA.x, A1v[0]); A1v[1] = fma2(cb2, qA.y, A1v[1]);
            A1v[2] = fma2(cb2, qB.x, A1v[2]); A1v[3] = fma2(cb2, qB.y, A1v[3]);
            float ns = sa*cda + ca*sda, nc = ca*cda - sa*sda; sa = ns; ca = nc;
            ns = sb*cdb + cb*sdb; nc = cb*cdb - sb*sdb; sb = ns; cb = nc;
        }
        ulonglong2 pA = Pu2[2 * 65], pB = Pu2[2 * 65 + 1];
        ull da2 = pk2(dya), db2 = pk2(dyb);
        A0v[0] = fma2(da2, pA.x, A0v[0]); A0v[1] = fma2(da2, pA.y, A0v[1]);
        A0v[2] = fma2(da2, pB.x, A0v[2]); A0v[3] = fma2(da2, pB.y, A0v[3]);
        A1v[0] = fma2(db2, pA.x, A1v[0]); A1v[1] = fma2(db2, pA.y, A1v[1]);
        A1v[2] = fma2(db2, pB.x, A1v[2]); A1v[3] = fma2(db2, pB.y, A1v[3]);
    }

    const float* csrow = g_sc + (size_t)i * NH * NN;
#pragma unroll
    for (int hp = 0; hp < 4; hp++) {
        float2 a0 = up2(A0v[hp]);
        float2 a1 = up2(A1v[hp]);
        int h0 = hp * 2, h1 = hp * 2 + 1;
        float2 cs0 = *(const float2*)&csrow[h0 * NN + ja];
        float2 cs1 = *(const float2*)&csrow[h1 * NN + ja];
        *(float2*)&s_s[h0][ja] = make_float2(cs0.x + a0.x * SCALE_F, cs0.y + a1.x * SCALE_F);
        *(float2*)&s_s[h1][ja] = make_float2(cs1.x + a0.y * SCALE_F, cs1.y + a1.y * SCALE_F);
    }
    __syncthreads();

    const int w = tid >> 5, lane = tid & 31;
    float4* s4 = (float4*)s_s[w];
    float m = -CUDART_INF_F;
#pragma unroll
    for (int t = 0; t < 4; t++) {
        float4 v = s4[lane + t * 32];
        m = fmaxf(m, fmaxf(fmaxf(v.x, v.y), fmaxf(v.z, v.w)));
    }
#pragma unroll
    for (int o = 16; o; o >>= 1) m = fmaxf(m, __shfl_xor_sync(0xffffffffu, m, o));
    float sum = 0.f;
#pragma unroll
    for (int t = 0; t < 4; t++) {
        float4 v = s4[lane + t * 32];
        v.x = __expf(v.x - m); v.y = __expf(v.y - m);
        v.z = __expf(v.z - m); v.w = __expf(v.w - m);
        s4[lane + t * 32] = v;
        sum += v.x + v.y + v.z + v.w;
    }
#pragma unroll
    for (int o = 16; o; o >>= 1) sum += __shfl_xor_sync(0xffffffffu, sum, o);
    const float inv = __fdividef(1.0f, sum);
    float4* arow = (float4*)(g_sc + (size_t)i * NH * NN + (size_t)w * NN);
#pragma unroll
    for (int t = 0; t < 4; t++) {
        float4 v = s4[lane + t * 32];
        arow[lane + t * 32] = make_float4(v.x * inv, v.y * inv, v.z * inv, v.w * inv);
    }
}

// ---------------- K4: attn @ V (tf32, 256 thr), split-K=4 --------------
__global__ void __launch_bounds__(256) av_kernel() {
    __shared__ unsigned At[64][68];
    __shared__ unsigned Vs[64][68];
    const int i0 = blockIdx.x * 64;
    const int h  = blockIdx.y;
    const int s  = blockIdx.z;
    const int kbase = s * 128;
    const int tid = threadIdx.x, w = tid >> 5, lane = tid & 31;
    const int wm = w & 1, wn = w >> 1;
    const int gid = lane >> 2, tig = lane & 3;

    float c[2][2][4] = {};
    for (int ch = 0; ch < 2; ch++) {
        const int kb = kbase + ch * 64;
#pragma unroll
        for (int i = 0; i < 4; i++) {
            int slot = tid + i * 256;
            int row = slot >> 4, c4 = slot & 15;
            float4 av = *(const float4*)&g_sc[((size_t)(i0 + row) * NH + h) * NN + kb + c4 * 4];
            *(uint4*)&At[row][c4 * 4] = f2t4(av);
            float4 vv = *(const float4*)&g_v[(size_t)(kb + row) * INNER + h * DH + c4 * 4];
            *(uint4*)&Vs[row][c4 * 4] = f2t4(vv);
        }
        __syncthreads();
#pragma unroll
        for (int kk = 0; kk < 8; kk++) {
            const int k0 = kk * 8;
            unsigned a[2][4], b[2][2];
#pragma unroll
            for (int am = 0; am < 2; am++) {
                int rb = wm * 32 + am * 16;
                a[am][0] = At[rb + gid][k0 + tig];
                a[am][1] = At[rb + gid + 8][k0 + tig];
                a[am][2] = At[rb + gid][k0 + tig + 4];
                a[am][3] = At[rb + gid + 8][k0 + tig + 4];
            }
#pragma unroll
            for (int an = 0; an < 2; an++) {
                int cb = wn * 16 + an * 8;
                b[an][0] = Vs[k0 + tig][cb + gid];
                b[an][1] = Vs[k0 + tig + 4][cb + gid];
            }
#pragma unroll
            for (int am = 0; am < 2; am++)
#pragma unroll
                for (int an = 0; an < 2; an++)
                    mma8(c[am][an], a[am], b[an]);
        }
        __syncthreads();
    }
#pragma unroll
    for (int am = 0; am < 2; am++) {
        int r0 = i0 + wm * 32 + am * 16 + gid;
#pragma unroll
        for (int an = 0; an < 2; an++) {
            int cc = h * DH + wn * 16 + an * 8 + tig * 2;
            float* d0 = &g_ao[((size_t)s * NN + r0) * INNER + cc];
            float* d1 = &g_ao[((size_t)s * NN + r0 + 8) * INNER + cc];
            *(float2*)d0 = make_float2(c[am][an][0], c[am][an][1]);
            *(float2*)d1 = make_float2(c[am][an][2], c[am][an][3]);
        }
    }
}

// ---------------- K5: out = (sum_s ao_s) @ Wo + bo (tf32, 128 thr) -----
__global__ void __launch_bounds__(128) out_kernel(const float* __restrict__ Wo,
                           const float* __restrict__ bo,
                           float* __restrict__ out) {
    __shared__ unsigned As[32][68];
    __shared__ unsigned Bs[64][68];
    const int n0 = blockIdx.x * 64;
    const int i0 = blockIdx.y * 32;
    const int tid = threadIdx.x, w = tid >> 5, lane = tid & 31;
    const int wm = w & 1, wn = w >> 1;
    const int gid = lane >> 2, tig = lane & 3;

    float c[4][4] = {};
    for (int ch = 0; ch < 8; ch++) {
        const int kb = ch * 64;
#pragma unroll
        for (int i = 0; i < 4; i++) {
            int slot = tid + i * 128;
            int row = slot >> 4, c4 = slot & 15;
            const float* base = g_ao + (size_t)(i0 + row) * INNER + kb + c4 * 4;
            float4 u0 = *(const float4*)(base);
            float4 u1 = *(const float4*)(base + (size_t)NN * INNER);
            float4 u2 = *(const float4*)(base + 2 * (size_t)NN * INNER);
            float4 u3 = *(const float4*)(base + 3 * (size_t)NN * INNER);
            float4 sum = make_float4(u0.x+u1.x+u2.x+u3.x, u0.y+u1.y+u2.y+u3.y,
                                     u0.z+u1.z+u2.z+u3.z, u0.w+u1.w+u2.w+u3.w);
            *(uint4*)&As[row][c4 * 4] = f2t4(sum);
        }
#pragma unroll
        for (int i = 0; i < 8; i++) {
            int slot = tid + i * 128;
            int row = slot >> 4, c4 = slot & 15;
            float4 bv = *(const float4*)&Wo[(size_t)(kb + row) * DIMX + n0 + c4 * 4];
            *(uint4*)&Bs[row][c4 * 4] = f2t4(bv);
        }
        __syncthreads();
#pragma unroll
        for (int kk = 0; kk < 8; kk++) {
            const int k0 = kk * 8;
            unsigned a[4], b[4][2];
            int rb = wm * 16;
            a[0] = As[rb + gid][k0 + tig];
            a[1] = As[rb + gid + 8][k0 + tig];
            a[2] = As[rb + gid][k0 + tig + 4];
            a[3] = As[rb + gid + 8][k0 + tig + 4];
#pragma unroll
            for (int an = 0; an < 4; an++) {
                int cb = wn * 32 + an * 8;
                b[an][0] = Bs[k0 + tig][cb + gid];
                b[an][1] = Bs[k0 + tig + 4][cb + gid];
            }
#pragma unroll
            for (int an = 0; an < 4; an++)
                mma8(c[an], a, b[an]);
        }
        __syncthreads();
    }
    int r0 = i0 + wm * 16 + gid;
#pragma unroll
    for (int an = 0; an < 4; an++) {
        int cc = n0 + wn * 32 + an * 8 + tig * 2;
        float b0 = bo[cc], b1 = bo[cc + 1];
        *(float2*)&out[(size_t)r0 * DIMX + cc] = make_float2(c[an][0] + b0, c[an][1] + b1);
        *(float2*)&out[(size_t)(r0 + 8) * DIMX + cc] = make_float2(c[an][2] + b0, c[an][3] + b1);
    }
}

// ---------------- launch ----------------------------------------------
extern "C" void kernel_launch(void* const* d_in, const int* in_sizes, int n_in,
                              void* d_out, int out_size) {
    const float* x   = (const float*)d_in[0];
    const float* pos = (const float*)d_in[1];
    const float* Wq  = (const float*)d_in[2];
    const float* Wk  = (const float*)d_in[3];
    const float* Wv  = (const float*)d_in[4];
    const float* Wo  = (const float*)d_in[5];
    const float* bo  = (const float*)d_in[6];
    float* out = (float*)d_out;

    cudaFuncSetAttribute(qkv_kernel, cudaFuncAttributeMaxDynamicSharedMemorySize, DB_SMEM);

    qkv_kernel<<<dim3(8, 8, 3), 128, DB_SMEM>>>(x, Wq, Wk, Wv);
    cs_kernel<<<dim3(8, 8, 8), 256>>>();
    p_kernel<<<256, 256>>>(Wk);
    rpe_softmax_kernel<<<512, 256>>>(pos);
    av_kernel<<<dim3(8, 8, KSPLIT), 256>>>();
    out_kernel<<<dim3(4, 16), 128>>>(Wo, bo, out);
}

// round 16
// speedup vs baseline: 1.4807x; 1.2231x over previous
#include <cuda_runtime.h>
#include <math_constants.h>

#define NN 512
#define DIMX 256
#define NH 8
#define DH 64
#define INNER 512
#define NR 66
#define PI_F 3.14159265358979f
#define SCALE_F 0.125f
#define INV_NORM (1.0f/51.0f)
#define DSTEP_F (7.0f*PI_F/15.0f)
#define KSPLIT 4
#define GRID_N 296

typedef unsigned long long ull;

// ---------------- scratch ----------------
__device__ float g_q [NN*INNER];
__device__ float g_kc[NN*INNER];
__device__ float g_v [NN*INNER];
__device__ float g_P [NN*NR*NH];                 // [i][r][h]
__device__ float g_sc[(size_t)NN*NH*NN];         // scores/attn, [i][h][j]
__device__ float g_ao[KSPLIT*(size_t)NN*INNER];  // split-K partials

// ---------------- grid barrier (generation-based, self-resetting) -----
__device__ unsigned g_arrive = 0;
__device__ volatile unsigned g_gen = 0;

static __device__ __forceinline__ void gbar() {
    __syncthreads();
    if (threadIdx.x == 0) {
        __threadfence();
        unsigned gen = g_gen;
        if (atomicAdd(&g_arrive, 1u) == gridDim.x - 1) {
            atomicExch(&g_arrive, 0u);
            __threadfence();
            g_gen = gen + 1;
        } else {
            while (g_gen == gen) __nanosleep(32);
        }
        __threadfence();
    }
    __syncthreads();
}

// ---------------- tf32 mma helpers ------------------------------------
static __device__ __forceinline__ unsigned f2t(float x) {
    unsigned u;
    asm("cvt.rna.tf32.f32 %0, %1;" : "=r"(u) : "f"(x));
    return u;
}
static __device__ __forceinline__ void mma8(float* c, const unsigned* a, const unsigned* b) {
    asm volatile(
        "mma.sync.aligned.m16n8k8.row.col.f32.tf32.tf32.f32 "
        "{%0,%1,%2,%3}, {%4,%5,%6,%7}, {%8,%9}, {%0,%1,%2,%3};"
        : "+f"(c[0]), "+f"(c[1]), "+f"(c[2]), "+f"(c[3])
        : "r"(a[0]), "r"(a[1]), "r"(a[2]), "r"(a[3]), "r"(b[0]), "r"(b[1]));
}
static __device__ __forceinline__ uint4 f2t4(float4 v) {
    return make_uint4(f2t(v.x), f2t(v.y), f2t(v.z), f2t(v.w));
}

// ---------------- f32x2 packed helpers ---------------------------------
static __device__ __forceinline__ ull pk2(float x) {
    ull d; unsigned u = __float_as_uint(x);
    asm("mov.b64 %0, {%1, %1};" : "=l"(d) : "r"(u));
    return d;
}
static __device__ __forceinline__ ull fma2(ull a, ull b, ull c) {
    ull d;
    asm("fma.rn.f32x2 %0, %1, %2, %3;" : "=l"(d) : "l"(a), "l"(b), "l"(c));
    return d;
}
static __device__ __forceinline__ float2 up2(ull d) {
    unsigned lo, hi;
    asm("mov.b64 {%0, %1}, %2;" : "=r"(lo), "=r"(hi) : "l"(d));
    return make_float2(__uint_as_float(lo), __uint_as_float(hi));
}

// ======================================================================
__global__ void __launch_bounds__(256, 2) fused_kernel(
        const float* __restrict__ x, const float* __restrict__ pos,
        const float* __restrict__ Wq, const float* __restrict__ Wk,
        const float* __restrict__ Wv, const float* __restrict__ Wo,
        const float* __restrict__ bo, float* __restrict__ out) {
    __shared__ unsigned sm[2 * 64 * 68];   // 34816 B, aliased per phase
    const int tid = threadIdx.x;
    const int w = tid >> 5, lane = tid & 31;
    const int gid = lane >> 2, tig = lane & 3;

    // ---------------- Phase 1: QKV (192 jobs, 256 thr, warp tile 32x16)
    for (int job = blockIdx.x; job < 192; job += gridDim.x) {
        const int z = job >> 6, rem = job & 63;
        const int m0 = (rem >> 3) * 64, n0 = (rem & 7) * 64;
        const float* W = (z == 0) ? Wq : ((z == 1) ? Wk : Wv);
        float* op = (z == 0) ? g_q : ((z == 1) ? g_kc : g_v);
        unsigned (*As)[68] = (unsigned(*)[68])sm;
        unsigned (*Bs)[68] = (unsigned(*)[68])(sm + 64 * 68);
        const int wm = w & 1, wn = w >> 1;

        float c[2][2][4] = {};
        for (int ch = 0; ch < 4; ch++) {
            const int kb = ch * 64;
#pragma unroll
            for (int i = 0; i < 4; i++) {
                int slot = tid + i * 256;
                int row = slot >> 4, c4 = slot & 15;
                float4 av = *(const float4*)&x[(size_t)(m0 + row) * DIMX + kb + c4 * 4];
                *(uint4*)&As[row][c4 * 4] = f2t4(av);
                float4 bv = *(const float4*)&W[(size_t)(kb + row) * INNER + n0 + c4 * 4];
                *(uint4*)&Bs[row][c4 * 4] = f2t4(bv);
            }
            __syncthreads();
#pragma unroll
            for (int kk = 0; kk < 8; kk++) {
                const int k0 = kk * 8;
                unsigned a[2][4], b[2][2];
#pragma unroll
                for (int am = 0; am < 2; am++) {
                    int rb = wm * 32 + am * 16;
                    a[am][0] = As[rb + gid][k0 + tig];
                    a[am][1] = As[rb + gid + 8][k0 + tig];
                    a[am][2] = As[rb + gid][k0 + tig + 4];
                    a[am][3] = As[rb + gid + 8][k0 + tig + 4];
                }
#pragma unroll
                for (int an = 0; an < 2; an++) {
                    int cb = wn * 16 + an * 8;
                    b[an][0] = Bs[k0 + tig][cb + gid];
                    b[an][1] = Bs[k0 + tig + 4][cb + gid];
                }
#pragma unroll
                for (int am = 0; am < 2; am++)
#pragma unroll
                    for (int an = 0; an < 2; an++)
                        mma8(c[am][an], a[am], b[an]);
            }
            __syncthreads();
        }
#pragma unroll
        for (int am = 0; am < 2; am++) {
            int r0 = m0 + wm * 32 + am * 16 + gid;
#pragma unroll
            for (int an = 0; an < 2; an++) {
                int cc = n0 + wn * 16 + an * 8 + tig * 2;
                *(float2*)&op[(size_t)r0 * INNER + cc] = make_float2(c[am][an][0], c[am][an][1]);
                *(float2*)&op[(size_t)(r0 + 8) * INNER + cc] = make_float2(c[am][an][2], c[am][an][3]);
            }
        }
    }
    gbar();

    // ---------------- Phase 2: content scores (512) + P (256) = 768 jobs
    for (int job = blockIdx.x; job < 768; job += gridDim.x) {
        if (job < 512) {
            const int h = job >> 6;
            const int i0 = ((job >> 3) & 7) * 64, j0 = (job & 7) * 64;
            unsigned (*Qs)[68] = (unsigned(*)[68])sm;
            unsigned (*Ks)[68] = (unsigned(*)[68])(sm + 64 * 68);
            const int wm = w & 1, wn = w >> 1;
#pragma unroll
            for (int i = 0; i < 4; i++) {
                int slot = tid + i * 256;
                int row = slot >> 4, c4 = slot & 15;
                float4 qv = *(const float4*)&g_q [(size_t)(i0 + row) * INNER + h * DH + c4 * 4];
                *(uint4*)&Qs[row][c4 * 4] = f2t4(qv);
                float4 kv = *(const float4*)&g_kc[(size_t)(j0 + row) * INNER + h * DH + c4 * 4];
                *(uint4*)&Ks[row][c4 * 4] = f2t4(kv);
            }
            __syncthreads();
            float c[2][2][4] = {};
#pragma unroll
            for (int kk = 0; kk < 8; kk++) {
                const int k0 = kk * 8;
                unsigned a[2][4], b[2][2];
#pragma unroll
                for (int am = 0; am < 2; am++) {
                    int rb = wm * 32 + am * 16;
                    a[am][0] = Qs[rb + gid][k0 + tig];
                    a[am][1] = Qs[rb + gid + 8][k0 + tig];
                    a[am][2] = Qs[rb + gid][k0 + tig + 4];
                    a[am][3] = Qs[rb + gid + 8][k0 + tig + 4];
                }
#pragma unroll
                for (int an = 0; an < 2; an++) {
                    int cb = wn * 16 + an * 8;
                    b[an][0] = Ks[cb + gid][k0 + tig];
                    b[an][1] = Ks[cb + gid][k0 + tig + 4];
                }
#pragma unroll
                for (int am = 0; am < 2; am++)
#pragma unroll
                    for (int an = 0; an < 2; an++)
                        mma8(c[am][an], a[am], b[an]);
            }
#pragma unroll
            for (int am = 0; am < 2; am++) {
                int r0 = i0 + wm * 32 + am * 16 + gid;
#pragma unroll
                for (int an = 0; an < 2; an++) {
                    int cc = j0 + wn * 16 + an * 8 + tig * 2;
                    float* d0 = &g_sc[((size_t)r0 * NH + h) * NN + cc];
                    float* d1 = &g_sc[((size_t)(r0 + 8) * NH + h) * NN + cc];
                    *(float2*)d0 = make_float2(c[am][an][0] * SCALE_F, c[am][an][1] * SCALE_F);
                    *(float2*)d1 = make_float2(c[am][an][2] * SCALE_F, c[am][an][3] * SCALE_F);
                }
            }
            __syncthreads();
        } else {
            // P for 2 queries
            float* qs = (float*)sm;
            const int i0 = (job - 512) * 2;
            const float4* src = (const float4*)(g_q + (size_t)i0 * INNER);
            ((float4*)qs)[tid] = src[tid];
            __syncthreads();
            for (int tt = tid; tt < 528; tt += 256) {
                int r = tt >> 3, h = tt & 7;
                const float4* w4 = (const float4*)(Wk + (size_t)(DIMX + r) * INNER + h * DH);
                float acc0 = 0.f, acc1 = 0.f;
#pragma unroll
                for (int u = 0; u < 16; u++) {
                    float4 wv = w4[u];
                    float4 q0 = *(const float4*)&qs[h * DH + u * 4];
                    float4 q1 = *(const float4*)&qs[INNER + h * DH + u * 4];
                    acc0 += wv.x*q0.x + wv.y*q0.y + wv.z*q0.z + wv.w*q0.w;
                    acc1 += wv.x*q1.x + wv.y*q1.y + wv.z*q1.z + wv.w*q1.w;
                }
                g_P[((size_t)i0 * NR + r) * NH + h] = acc0;
                g_P[((size_t)(i0 + 1) * NR + r) * NH + h] = acc1;
            }
            __syncthreads();
        }
    }
    gbar();

    // ---------------- Phase 3: RPE + softmax (512 jobs)
    for (int job = blockIdx.x; job < 512; job += gridDim.x) {
        const int i = job;
        float* Ps = (float*)sm;                       // 528 floats
        float (*s_s)[NN] = (float(*)[NN])(sm + 528);  // 8x512 floats
        for (int t = tid; t < NR * NH; t += 256) Ps[t] = g_P[(size_t)i * NR * NH + t];
        __syncthreads();

        const float2 pq = ((const float2*)pos)[i];
        const ulonglong2* Pu2 = reinterpret_cast<const ulonglong2*>(Ps);

        const int ja = tid * 2;
        const float4 pk = *(const float4*)&pos[ja * 2];
        float dxa = (pk.x - pq.x) * INV_NORM; dxa = __fdividef(dxa, 1.f + fabsf(dxa));
        float dya = (pk.y - pq.y) * INV_NORM; dya = __fdividef(dya, 1.f + fabsf(dya));
        float dxb = (pk.z - pq.x) * INV_NORM; dxb = __fdividef(dxb, 1.f + fabsf(dxb));
        float dyb = (pk.w - pq.y) * INV_NORM; dyb = __fdividef(dyb, 1.f + fabsf(dyb));

        ull A0v[4] = {}, A1v[4] = {};
        {
            float sa, ca, sb, cb, sda, cda, sdb, cdb;
            __sincosf(dxa * PI_F, &sa, &ca);  __sincosf(dxa * DSTEP_F, &sda, &cda);
            __sincosf(dxb * PI_F, &sb, &cb);  __sincosf(dxb * DSTEP_F, &sdb, &cdb);
#pragma unroll
            for (int k = 0; k < 16; k++) {
                ulonglong2 pA = Pu2[2 * k],        pB = Pu2[2 * k + 1];
                ulonglong2 qA = Pu2[2 * (16 + k)], qB = Pu2[2 * (16 + k) + 1];
                ull sa2 = pk2(sa), ca2 = pk2(ca), sb2 = pk2(sb), cb2 = pk2(cb);
                A0v[0] = fma2(sa2, pA.x, A0v[0]); A0v[1] = fma2(sa2, pA.y, A0v[1]);
                A0v[2] = fma2(sa2, pB.x, A0v[2]); A0v[3] = fma2(sa2, pB.y, A0v[3]);
                A0v[0] = fma2(ca2, qA.x, A0v[0]); A0v[1] = fma2(ca2, qA.y, A0v[1]);
                A0v[2] = fma2(ca2, qB.x, A0v[2]); A0v[3] = fma2(ca2, qB.y, A0v[3]);
                A1v[0] = fma2(sb2, pA.x, A1v[0]); A1v[1] = fma2(sb2, pA.y, A1v[1]);
                A1v[2] = fma2(sb2, pB.x, A1v[2]); A1v[3] = fma2(sb2, pB.y, A1v[3]);
                A1v[0] = fma2(cb2, qA.x, A1v[0]); A1v[1] = fma2(cb2, qA.y, A1v[1]);
                A1v[2] = fma2(cb2, qB.x, A1v[2]); A1v[3] = fma2(cb2, qB.y, A1v[3]);
                float ns = sa*cda + ca*sda, nc = ca*cda - sa*sda; sa = ns; ca = nc;
                ns = sb*cdb + cb*sdb; nc = cb*cdb - sb*sdb; sb = ns; cb = nc;
            }
            ulonglong2 pA = Pu2[2 * 32], pB = Pu2[2 * 32 + 1];
            ull da2 = pk2(dxa), db2 = pk2(dxb);
            A0v[0] = fma2(da2, pA.x, A0v[0]); A0v[1] = fma2(da2, pA.y, A0v[1]);
            A0v[2] = fma2(da2, pB.x, A0v[2]); A0v[3] = fma2(da2, pB.y, A0v[3]);
            A1v[0] = fma2(db2, pA.x, A1v[0]); A1v[1] = fma2(db2, pA.y, A1v[1]);
            A1v[2] = fma2(db2, pB.x, A1v[2]); A1v[3] = fma2(db2, pB.y, A1v[3]);
        }
        {
            float sa, ca, sb, cb, sda, cda, sdb, cdb;
            __sincosf(dya * PI_F, &sa, &ca);  __sincosf(dya * DSTEP_F, &sda, &cda);
            __sincosf(dyb * PI_F, &sb, &cb);  __sincosf(dyb * DSTEP_F, &sdb, &cdb);
#pragma unroll
            for (int k = 0; k < 16; k++) {
                ulonglong2 pA = Pu2[2 * (33 + k)], pB = Pu2[2 * (33 + k) + 1];
                ulonglong2 qA = Pu2[2 * (49 + k)], qB = Pu2[2 * (49 + k) + 1];
                ull sa2 = pk2(sa), ca2 = pk2(ca), sb2 = pk2(sb), cb2 = pk2(cb);
                A0v[0] = fma2(sa2, pA.x, A0v[0]); A0v[1] = fma2(sa2, pA.y, A0v[1]);
                A0v[2] = fma2(sa2, pB.x, A0v[2]); A0v[3] = fma2(sa2, pB.y, A0v[3]);
                A0v[0] = fma2(ca2, qA.x, A0v[0]); A0v[1] = fma2(ca2, qA.y, A0v[1]);
                A0v[2] = fma2(ca2, qB.x, A0v[2]); A0v[3] = fma2(ca2, qB.y, A0v[3]);
                A1v[0] = fma2(sb2, pA.x, A1v[0]); A1v[1] = fma2(sb2, pA.y, A1v[1]);
                A1v[2] = fma2(sb2, pB.x, A1v[2]); A1v[3] = fma2(sb2, pB.y, A1v[3]);
                A1v[0] = fma2(cb2, qA.x, A1v[0]); A1v[1] = fma2(cb2, qA.y, A1v[1]);
                A1v[2] = fma2(cb2, qB.x, A1v[2]); A1v[3] = fma2(cb2, qB.y, A1v[3]);
                float ns = sa*cda + ca*sda, nc = ca*cda - sa*sda; sa = ns; ca = nc;
                ns = sb*cdb + cb*sdb; nc = cb*cdb - sb*sdb; sb = ns; cb = nc;
            }
            ulonglong2 pA = Pu2[2 * 65], pB = Pu2[2 * 65 + 1];
            ull da2 = pk2(dya), db2 = pk2(dyb);
            A0v[0] = fma2(da2, pA.x, A0v[0]); A0v[1] = fma2(da2, pA.y, A0v[1]);
            A0v[2] = fma2(da2, pB.x, A0v[2]); A0v[3] = fma2(da2, pB.y, A0v[3]);
            A1v[0] = fma2(db2, pA.x, A1v[0]); A1v[1] = fma2(db2, pA.y, A1v[1]);
            A1v[2] = fma2(db2, pB.x, A1v[2]); A1v[3] = fma2(db2, pB.y, A1v[3]);
        }

        const float* csrow = g_sc + (size_t)i * NH * NN;
#pragma unroll
        for (int hp = 0; hp < 4; hp++) {
            float2 a0 = up2(A0v[hp]);
            float2 a1 = up2(A1v[hp]);
            int h0 = hp * 2, h1 = hp * 2 + 1;
            float2 cs0 = *(const float2*)&csrow[h0 * NN + ja];
            float2 cs1 = *(const float2*)&csrow[h1 * NN + ja];
            *(float2*)&s_s[h0][ja] = make_float2(cs0.x + a0.x * SCALE_F, cs0.y + a1.x * SCALE_F);
            *(float2*)&s_s[h1][ja] = make_float2(cs1.x + a0.y * SCALE_F, cs1.y + a1.y * SCALE_F);
        }
        __syncthreads();

        float4* s4 = (float4*)s_s[w];
        float m = -CUDART_INF_F;
#pragma unroll
        for (int t = 0; t < 4; t++) {
            float4 v = s4[lane + t * 32];
            m = fmaxf(m, fmaxf(fmaxf(v.x, v.y), fmaxf(v.z, v.w)));
        }
#pragma unroll
        for (int o = 16; o; o >>= 1) m = fmaxf(m, __shfl_xor_sync(0xffffffffu, m, o));
        float sum = 0.f;
#pragma unroll
        for (int t = 0; t < 4; t++) {
            float4 v = s4[lane + t * 32];
            v.x = __expf(v.x - m); v.y = __expf(v.y - m);
            v.z = __expf(v.z - m); v.w = __expf(v.w - m);
            s4[lane + t * 32] = v;
            sum += v.x + v.y + v.z + v.w;
        }
#pragma unroll
        for (int o = 16; o; o >>= 1) sum += __shfl_xor_sync(0xffffffffu, sum, o);
        const float inv = __fdividef(1.0f, sum);
        float4* arow = (float4*)(g_sc + (size_t)i * NH * NN + (size_t)w * NN);
#pragma unroll
        for (int t = 0; t < 4; t++) {
            float4 v = s4[lane + t * 32];
            arow[lane + t * 32] = make_float4(v.x * inv, v.y * inv, v.z * inv, v.w * inv);
        }
        __syncthreads();
    }
    gbar();

    // ---------------- Phase 4: attn @ V (256 jobs, split-K=4)
    for (int job = blockIdx.x; job < 256; job += gridDim.x) {
        const int s  = job >> 6;
        const int h  = (job >> 3) & 7;
        const int i0 = (job & 7) * 64;
        const int kbase = s * 128;
        unsigned (*At)[68] = (unsigned(*)[68])sm;
        unsigned (*Vs)[68] = (unsigned(*)[68])(sm + 64 * 68);
        const int wm = w & 1, wn = w >> 1;

        float c[2][2][4] = {};
        for (int ch = 0; ch < 2; ch++) {
            const int kb = kbase + ch * 64;
#pragma unroll
            for (int i = 0; i < 4; i++) {
                int slot = tid + i * 256;
                int row = slot >> 4, c4 = slot & 15;
                float4 av = __ldcg((const float4*)&g_sc[((size_t)(i0 + row) * NH + h) * NN + kb + c4 * 4]);
                *(uint4*)&At[row][c4 * 4] = f2t4(av);
                float4 vv = *(const float4*)&g_v[(size_t)(kb + row) * INNER + h * DH + c4 * 4];
                *(uint4*)&Vs[row][c4 * 4] = f2t4(vv);
            }
            __syncthreads();
#pragma unroll
            for (int kk = 0; kk < 8; kk++) {
                const int k0 = kk * 8;
                unsigned a[2][4], b[2][2];
#pragma unroll
                for (int am = 0; am < 2; am++) {
                    int rb = wm * 32 + am * 16;
                    a[am][0] = At[rb + gid][k0 + tig];
                    a[am][1] = At[rb + gid + 8][k0 + tig];
                    a[am][2] = At[rb + gid][k0 + tig + 4];
                    a[am][3] = At[rb + gid + 8][k0 + tig + 4];
                }
#pragma unroll
                for (int an = 0; an < 2; an++) {
                    int cb = wn * 16 + an * 8;
                    b[an][0] = Vs[k0 + tig][cb + gid];
                    b[an][1] = Vs[k0 + tig + 4][cb + gid];
                }
#pragma unroll
                for (int am = 0; am < 2; am++)
#pragma unroll
                    for (int an = 0; an < 2; an++)
                        mma8(c[am][an], a[am], b[an]);
            }
            __syncthreads();
        }
#pragma unroll
        for (int am = 0; am < 2; am++) {
            int r0 = i0 + wm * 32 + am * 16 + gid;
#pragma unroll
            for (int an = 0; an < 2; an++) {
                int cc = h * DH + wn * 16 + an * 8 + tig * 2;
                float* d0 = &g_ao[((size_t)s * NN + r0) * INNER + cc];
                float* d1 = &g_ao[((size_t)s * NN + r0 + 8) * INNER + cc];
                *(float2*)d0 = make_float2(c[am][an][0], c[am][an][1]);
                *(float2*)d1 = make_float2(c[am][an][2], c[am][an][3]);
            }
        }
    }
    gbar();

    // ---------------- Phase 5: out (128 jobs, tile 16x64, warp m16n8)
    for (int job = blockIdx.x; job < 128; job += gridDim.x) {
        const int n0 = (job & 3) * 64;
        const int i0 = (job >> 2) * 16;
        unsigned (*As)[68] = (unsigned(*)[68])sm;             // [16][68]
        unsigned (*Bs)[68] = (unsigned(*)[68])(sm + 16 * 68); // [64][68]
        const int wn = w;

        float c[4] = {};
        for (int ch = 0; ch < 8; ch++) {
            const int kb = ch * 64;
            {
                int row = tid >> 4, c4 = tid & 15;
                const float* base = g_ao + (size_t)(i0 + row) * INNER + kb + c4 * 4;
                float4 u0 = *(const float4*)(base);
                float4 u1 = *(const float4*)(base + (size_t)NN * INNER);
                float4 u2 = *(const float4*)(base + 2 * (size_t)NN * INNER);
                float4 u3 = *(const float4*)(base + 3 * (size_t)NN * INNER);
                float4 sum = make_float4(u0.x+u1.x+u2.x+u3.x, u0.y+u1.y+u2.y+u3.y,
                                         u0.z+u1.z+u2.z+u3.z, u0.w+u1.w+u2.w+u3.w);
                *(uint4*)&As[row][c4 * 4] = f2t4(sum);
            }
#pragma unroll
            for (int i = 0; i < 4; i++) {
                int slot = tid + i * 256;
                int row = slot >> 4, c4 = slot & 15;
                float4 bv = *(const float4*)&Wo[(size_t)(kb + row) * DIMX + n0 + c4 * 4];
                *(uint4*)&Bs[row][c4 * 4] = f2t4(bv);
            }
            __syncthreads();
#pragma unroll
            for (int kk = 0; kk < 8; kk++) {
                const int k0 = kk * 8;
                unsigned a[4], b[2];
                a[0] = As[gid][k0 + tig];
                a[1] = As[gid + 8][k0 + tig];
                a[2] = As[gid][k0 + tig + 4];
                a[3] = As[gid + 8][k0 + tig + 4];
                b[0] = Bs[k0 + tig][wn * 8 + gid];
                b[1] = Bs[k0 + tig + 4][wn * 8 + gid];
                mma8(c, a, b);
            }
            __syncthreads();
        }
        int r0 = i0 + gid;
        int cc = n0 + wn * 8 + tig * 2;
        float b0 = bo[cc], b1 = bo[cc + 1];
        *(float2*)&out[(size_t)r0 * DIMX + cc] = make_float2(c[0] + b0, c[1] + b1);
        *(float2*)&out[(size_t)(r0 + 8) * DIMX + cc] = make_float2(c[2] + b0, c[3] + b1);
    }
}

// ---------------- launch ----------------------------------------------
extern "C" void kernel_launch(void* const* d_in, const int* in_sizes, int n_in,
                              void* d_out, int out_size) {
    const float* x   = (const float*)d_in[0];
    const float* pos = (const float*)d_in[1];
    const float* Wq  = (const float*)d_in[2];
    const float* Wk  = (const float*)d_in[3];
    const float* Wv  = (const float*)d_in[4];
    const float* Wo  = (const float*)d_in[5];
    const float* bo  = (const float*)d_in[6];
    float* out = (float*)d_out;

    fused_kernel<<<GRID_N, 256>>>(x, pos, Wq, Wk, Wv, Wo, bo, out);
}